// round 8
// baseline (speedup 1.0000x reference)
#include <cuda_runtime.h>
#include <cuda_bf16.h>
#include <mma.h>
#include <cstdint>

using namespace nvcuda;

#define B_    8
#define N_    256
#define C_    512
#define HW_   64
#define DIM_  1024
#define M_    (B_ * N_)          // 2048

// ---------------- device scratch (no allocation allowed) -------------------
__device__ float g_z[M_ * DIM_];     // unscaled projections, tf32-rounded (8 MB)
__device__ float g_fcw[DIM_ * DIM_]; // tf32-rounded copy of fc_w (4 MB)
__device__ float g_msum[M_];         // per-(b,n) sum over (C,H,W)
__device__ float g_s[M_];            // a1*a2*a3 per (b,n)
__device__ float g_cvec[DIM_];       // bs_vec @ fc_w^T + fc_b

// ---------------- cp.async helpers -----------------------------------------
#define CP_ASYNC16(dst_u32, src_ptr) \
    asm volatile("cp.async.cg.shared.global [%0], [%1], 16;\n" \
                 :: "r"(dst_u32), "l"(src_ptr))
#define CP_COMMIT()  asm volatile("cp.async.commit_group;\n" ::)
#define CP_WAIT2()   asm volatile("cp.async.wait_group 2;\n" ::)
#define CP_WAIT0()   asm volatile("cp.async.wait_group 0;\n" ::)

// ===========================================================================
// K1: single fused pass over x (256 MB, read exactly once).
// Half-warp (16 lanes x float4 = 64 floats = one channel slab, 256B coalesced).
// Each warp covers 2 channels; block = 8 warps = 16 channels/iter, 32 iters.
// Ws (2 float4 per lane) amortized over 4 consecutive n values.
// Emits tf32-rounded z[m][2c],z[m][2c+1] and msum (deterministic reduction).
// ===========================================================================
__global__ __launch_bounds__(256)
void k_reduce(const float4* __restrict__ x4, const float4* __restrict__ Ws4)
{
    const int m0   = blockIdx.x * 4;          // 512 blocks -> m = b*256+n
    const int tid  = threadIdx.x;
    const int warp = tid >> 5;
    const int lane = tid & 31;
    const int half = lane >> 4;               // which channel within the warp
    const int hl   = lane & 15;               // lane within half-warp

    float sum0 = 0.f, sum1 = 0.f, sum2 = 0.f, sum3 = 0.f;

    #pragma unroll 1
    for (int it = 0; it < 32; ++it) {
        const int c = it * 16 + warp * 2 + half;
        const float4 w0 = Ws4[c * 32 + hl];
        const float4 w1 = Ws4[c * 32 + 16 + hl];

        // batch the 4 independent loads first (MLP=4 per lane)
        float4 xv[4];
        #pragma unroll
        for (int nt = 0; nt < 4; ++nt)
            xv[nt] = x4[((m0 + nt) * C_ + c) * 16 + hl];

        #pragma unroll
        for (int nt = 0; nt < 4; ++nt) {
            const float4 v = xv[nt];
            float z0 = v.x * w0.x + v.y * w0.y + v.z * w0.z + v.w * w0.w;
            float z1 = v.x * w1.x + v.y * w1.y + v.z * w1.z + v.w * w1.w;
            const float ls = (v.x + v.y) + (v.z + v.w);
            if (nt == 0) sum0 += ls; else if (nt == 1) sum1 += ls;
            else if (nt == 2) sum2 += ls; else sum3 += ls;
            #pragma unroll
            for (int off = 8; off; off >>= 1) {
                z0 += __shfl_xor_sync(0xffffffffu, z0, off);
                z1 += __shfl_xor_sync(0xffffffffu, z1, off);
            }
            if (hl == 0) {
                float2 zz = make_float2(wmma::__float_to_tf32(z0),
                                        wmma::__float_to_tf32(z1));
                *(float2*)&g_z[(m0 + nt) * DIM_ + 2 * c] = zz;
            }
        }
    }

    #pragma unroll
    for (int off = 16; off; off >>= 1) {
        sum0 += __shfl_xor_sync(0xffffffffu, sum0, off);
        sum1 += __shfl_xor_sync(0xffffffffu, sum1, off);
        sum2 += __shfl_xor_sync(0xffffffffu, sum2, off);
        sum3 += __shfl_xor_sync(0xffffffffu, sum3, off);
    }
    __shared__ float red[8][4];
    if (lane == 0) {
        red[warp][0] = sum0; red[warp][1] = sum1;
        red[warp][2] = sum2; red[warp][3] = sum3;
    }
    __syncthreads();
    if (tid < 4) {
        float t = 0.f;
        #pragma unroll
        for (int w = 0; w < 8; ++w) t += red[w][tid];
        g_msum[m0 + tid] = t;
    }
}

// ===========================================================================
// K2: attention chain on the 2048-element mean vector. One block per b.
// ===========================================================================
__global__ __launch_bounds__(256)
void k_att(const float* __restrict__ conv_w, const float* __restrict__ conv_b)
{
    const int b = blockIdx.x;
    const int n = threadIdx.x;
    __shared__ float sm_m[N_];
    sm_m[n] = g_msum[b * N_ + n] * (1.0f / 32768.0f);   // mean over C*H*W
    float stot = 1.f;
    #pragma unroll
    for (int i = 0; i < 3; ++i) {
        __syncthreads();
        float acc = conv_b[i];
        #pragma unroll
        for (int j = 0; j < 5; ++j) {
            const int idx = n + j - 2;
            const float v = (idx >= 0 && idx < N_) ? sm_m[idx] : 0.f;
            acc += v * conv_w[i * 5 + j];
        }
        const float att = 1.0f / (1.0f + __expf(-acc));
        stot *= att;
        __syncthreads();
        sm_m[n] *= att;
    }
    g_s[b * N_ + n] = stot;
}

// ===========================================================================
// K3: cvec[d] = sum_k bs_vec[k]*fc_w[d,k] + fc_b[d]  (full precision), and
// also emit the tf32-rounded copy of fc_w for the GEMM. One warp per d.
// ===========================================================================
__global__ __launch_bounds__(256)
void k_cvec(const float* __restrict__ bs, const float* __restrict__ fc_w,
            const float* __restrict__ fc_b)
{
    const int gw   = (blockIdx.x * blockDim.x + threadIdx.x) >> 5;  // d
    const int lane = threadIdx.x & 31;
    float acc = 0.f;
    for (int k = lane; k < DIM_; k += 32) {
        const float v = fc_w[gw * DIM_ + k];
        acc += bs[k] * v;
        g_fcw[gw * DIM_ + k] = wmma::__float_to_tf32(v);
    }
    #pragma unroll
    for (int off = 16; off; off >>= 1)
        acc += __shfl_xor_sync(0xffffffffu, acc, off);
    if (lane == 0) g_cvec[gw] = acc + fc_b[gw];
}

// ===========================================================================
// K4: out[m,d] = s[m] * (z @ fcw^T)[m,d] + cvec[d]
// tf32 wmma m16n16k8. CTA tile 128x128, BK=32, 4-stage cp.async pipeline,
// 512 threads = 16 warps (4x4), warp tile 32x32 (2x2 frags). No per-stage
// conversion (operands pre-rounded). Epilogue through smem, scaled store.
// ===========================================================================
#define BM     128
#define BN     128
#define BK     32
#define LDA    36      // BK + 4 pad; 144 B rows keep 16B alignment, shift banks
#define LDC    132
#define STAGES 4
#define TILE_F (BM * LDA)                  // floats per A (or B) stage

__global__ __launch_bounds__(512)
void k_gemm(float* __restrict__ out)
{
    extern __shared__ float sm[];
    float* As = sm;                         // [STAGES][BM][LDA]
    float* Bs = sm + STAGES * TILE_F;       // [STAGES][BN][LDA]

    const int tid  = threadIdx.x;
    const int warp = tid >> 5;
    const int wm   = warp >> 2;             // 0..3
    const int wn   = warp & 3;              // 0..3
    const int m_cta = blockIdx.y * BM;      // 16 tiles
    const int n_cta = blockIdx.x * BN;      // 8 tiles

    // loader mapping: 512 threads * 16B = 8 KB per pass; 2 passes per tile
    const int lrow = tid >> 3;              // 0..63
    const int lcol = (tid & 7) * 4;         // float col group

    wmma::fragment<wmma::accumulator, 16, 16, 8, float> acc[2][2];
    #pragma unroll
    for (int i = 0; i < 2; ++i)
        #pragma unroll
        for (int j = 0; j < 2; ++j)
            wmma::fill_fragment(acc[i][j], 0.0f);

    // prologue: prime 3 stages
    #pragma unroll
    for (int t = 0; t < STAGES - 1; ++t) {
        const int s  = t;
        const int k0 = t * BK;
        #pragma unroll
        for (int r = 0; r < 2; ++r) {
            const int rw = lrow + r * 64;
            const uint32_t da = (uint32_t)__cvta_generic_to_shared(
                &As[s * TILE_F + rw * LDA + lcol]);
            CP_ASYNC16(da, &g_z[(m_cta + rw) * DIM_ + k0 + lcol]);
            const uint32_t db = (uint32_t)__cvta_generic_to_shared(
                &Bs[s * TILE_F + rw * LDA + lcol]);
            CP_ASYNC16(db, &g_fcw[(n_cta + rw) * DIM_ + k0 + lcol]);
        }
        CP_COMMIT();
    }

    const int NSTAGE = DIM_ / BK;           // 32
    #pragma unroll 1
    for (int t = 0; t < NSTAGE; ++t) {
        CP_WAIT2();                          // stage t resident
        __syncthreads();                     // all warps done with stage t-? reuse

        // prefetch stage t+3 (overwrites buffer consumed at iter t-1)
        if (t + STAGES - 1 < NSTAGE) {
            const int s  = (t + STAGES - 1) & (STAGES - 1);
            const int k0 = (t + STAGES - 1) * BK;
            #pragma unroll
            for (int r = 0; r < 2; ++r) {
                const int rw = lrow + r * 64;
                const uint32_t da = (uint32_t)__cvta_generic_to_shared(
                    &As[s * TILE_F + rw * LDA + lcol]);
                CP_ASYNC16(da, &g_z[(m_cta + rw) * DIM_ + k0 + lcol]);
                const uint32_t db = (uint32_t)__cvta_generic_to_shared(
                    &Bs[s * TILE_F + rw * LDA + lcol]);
                CP_ASYNC16(db, &g_fcw[(n_cta + rw) * DIM_ + k0 + lcol]);
            }
        }
        CP_COMMIT();                         // keep group count in lockstep

        // compute stage t
        const int s = t & (STAGES - 1);
        #pragma unroll
        for (int kk = 0; kk < BK; kk += 8) {
            wmma::fragment<wmma::matrix_a, 16, 16, 8, wmma::precision::tf32, wmma::row_major> af[2];
            wmma::fragment<wmma::matrix_b, 16, 16, 8, wmma::precision::tf32, wmma::col_major> bf[2];
            #pragma unroll
            for (int i = 0; i < 2; ++i)
                wmma::load_matrix_sync(af[i], &As[s * TILE_F + (wm * 32 + i * 16) * LDA + kk], LDA);
            #pragma unroll
            for (int j = 0; j < 2; ++j)
                wmma::load_matrix_sync(bf[j], &Bs[s * TILE_F + (wn * 32 + j * 16) * LDA + kk], LDA);
            #pragma unroll
            for (int i = 0; i < 2; ++i)
                #pragma unroll
                for (int j = 0; j < 2; ++j)
                    wmma::mma_sync(acc[i][j], af[i], bf[j], acc[i][j]);
        }
    }

    CP_WAIT0();
    __syncthreads();

    // epilogue: stage through smem, then scaled coalesced store
    float* Cs = sm;                          // 128*132*4 = 67.6 KB (fits)
    #pragma unroll
    for (int i = 0; i < 2; ++i)
        #pragma unroll
        for (int j = 0; j < 2; ++j)
            wmma::store_matrix_sync(&Cs[(wm * 32 + i * 16) * LDC + wn * 32 + j * 16],
                                    acc[i][j], LDC, wmma::mem_row_major);
    __syncthreads();

    #pragma unroll
    for (int r = 0; r < 8; ++r) {
        const int idx = tid + r * 512;       // 0..4095
        const int rw  = idx >> 5;            // row 0..127
        const int cc  = (idx & 31) * 4;      // col group
        const float4 cv = *(const float4*)&Cs[rw * LDC + cc];
        const float4 bv = *(const float4*)&g_cvec[n_cta + cc];
        const float  sc = g_s[m_cta + rw];
        float4 o;
        o.x = sc * cv.x + bv.x;
        o.y = sc * cv.y + bv.y;
        o.z = sc * cv.z + bv.z;
        o.w = sc * cv.w + bv.w;
        *(float4*)&out[(m_cta + rw) * DIM_ + n_cta + cc] = o;
    }
}

// ===========================================================================
extern "C" void kernel_launch(void* const* d_in, const int* in_sizes, int n_in,
                              void* d_out, int out_size)
{
    (void)in_sizes; (void)n_in; (void)out_size;
    const float* x      = (const float*)d_in[0];
    const float* conv_w = (const float*)d_in[1];
    const float* conv_b = (const float*)d_in[2];
    const float* Ws     = (const float*)d_in[3];
    const float* bs     = (const float*)d_in[4];
    const float* fc_w   = (const float*)d_in[5];
    const float* fc_b   = (const float*)d_in[6];
    float* out = (float*)d_out;

    k_reduce<<<M_ / 4, 256>>>((const float4*)x, (const float4*)Ws);
    k_att<<<B_, 256>>>(conv_w, conv_b);
    k_cvec<<<DIM_ / 8, 256>>>(bs, fc_w, fc_b);

    const int smem = 2 * STAGES * TILE_F * (int)sizeof(float);  // 147456 B
    cudaFuncSetAttribute(k_gemm, cudaFuncAttributeMaxDynamicSharedMemorySize, smem);
    dim3 grid(DIM_ / BN, M_ / BM);          // (8, 16) = 128 CTAs, one wave
    k_gemm<<<grid, 256 * 2, smem>>>(out);
}

// round 13
// speedup vs baseline: 1.3769x; 1.3769x over previous
#include <cuda_runtime.h>
#include <cuda_bf16.h>
#include <mma.h>
#include <cstdint>

using namespace nvcuda;

#define B_    8
#define N_    256
#define C_    512
#define HW_   64
#define DIM_  1024
#define M_    (B_ * N_)          // 2048

// ---------------- device scratch (no allocation allowed) -------------------
__device__ float g_z[M_ * DIM_];     // unscaled projections, tf32-rounded (8 MB)
__device__ float g_fcw[DIM_ * DIM_]; // tf32-rounded copy of fc_w (4 MB)
__device__ float g_msum[M_];         // per-(b,n) sum over (C,H,W)
__device__ float g_s[M_];            // a1*a2*a3 per (b,n)
__device__ float g_cvec[DIM_];       // bs_vec @ fc_w^T + fc_b

// ---------------- PTX helpers (all sm_80-era: safe on compute_103) ---------
#define CP_ASYNC16(dst_u32, src_ptr) \
    asm volatile("cp.async.cg.shared.global [%0], [%1], 16;\n" \
                 :: "r"(dst_u32), "l"(src_ptr))
#define CP_COMMIT()  asm volatile("cp.async.commit_group;\n" ::)
#define CP_WAIT2()   asm volatile("cp.async.wait_group 2;\n" ::)

#define LDSM_X4(r, addr) \
    asm volatile("ldmatrix.sync.aligned.m8n8.x4.shared.b16 {%0,%1,%2,%3}, [%4];" \
        : "=r"((r)[0]), "=r"((r)[1]), "=r"((r)[2]), "=r"((r)[3]) : "r"(addr))

#define MMA_TF32(d, a, b0v, b1v) \
    asm volatile("mma.sync.aligned.m16n8k8.row.col.f32.tf32.tf32.f32 " \
        "{%0,%1,%2,%3}, {%4,%5,%6,%7}, {%8,%9}, {%0,%1,%2,%3};" \
        : "+f"((d)[0]), "+f"((d)[1]), "+f"((d)[2]), "+f"((d)[3]) \
        : "r"((a)[0]), "r"((a)[1]), "r"((a)[2]), "r"((a)[3]), \
          "r"(b0v), "r"(b1v))

// ===========================================================================
// K1: single fused pass over x (256 MB, read exactly once).
// ===========================================================================
__global__ __launch_bounds__(256)
void k_reduce(const float4* __restrict__ x4, const float4* __restrict__ Ws4)
{
    const int m0   = blockIdx.x * 4;
    const int tid  = threadIdx.x;
    const int warp = tid >> 5;
    const int lane = tid & 31;
    const int half = lane >> 4;
    const int hl   = lane & 15;

    float sum0 = 0.f, sum1 = 0.f, sum2 = 0.f, sum3 = 0.f;

    #pragma unroll 1
    for (int it = 0; it < 32; ++it) {
        const int c = it * 16 + warp * 2 + half;
        const float4 w0 = Ws4[c * 32 + hl];
        const float4 w1 = Ws4[c * 32 + 16 + hl];

        float4 xv[4];
        #pragma unroll
        for (int nt = 0; nt < 4; ++nt)
            xv[nt] = x4[((m0 + nt) * C_ + c) * 16 + hl];

        #pragma unroll
        for (int nt = 0; nt < 4; ++nt) {
            const float4 v = xv[nt];
            float z0 = v.x * w0.x + v.y * w0.y + v.z * w0.z + v.w * w0.w;
            float z1 = v.x * w1.x + v.y * w1.y + v.z * w1.z + v.w * w1.w;
            const float ls = (v.x + v.y) + (v.z + v.w);
            if (nt == 0) sum0 += ls; else if (nt == 1) sum1 += ls;
            else if (nt == 2) sum2 += ls; else sum3 += ls;
            #pragma unroll
            for (int off = 8; off; off >>= 1) {
                z0 += __shfl_xor_sync(0xffffffffu, z0, off);
                z1 += __shfl_xor_sync(0xffffffffu, z1, off);
            }
            if (hl == 0) {
                float2 zz = make_float2(wmma::__float_to_tf32(z0),
                                        wmma::__float_to_tf32(z1));
                *(float2*)&g_z[(m0 + nt) * DIM_ + 2 * c] = zz;
            }
        }
    }

    #pragma unroll
    for (int off = 16; off; off >>= 1) {
        sum0 += __shfl_xor_sync(0xffffffffu, sum0, off);
        sum1 += __shfl_xor_sync(0xffffffffu, sum1, off);
        sum2 += __shfl_xor_sync(0xffffffffu, sum2, off);
        sum3 += __shfl_xor_sync(0xffffffffu, sum3, off);
    }
    __shared__ float red[8][4];
    if (lane == 0) {
        red[warp][0] = sum0; red[warp][1] = sum1;
        red[warp][2] = sum2; red[warp][3] = sum3;
    }
    __syncthreads();
    if (tid < 4) {
        float t = 0.f;
        #pragma unroll
        for (int w = 0; w < 8; ++w) t += red[w][tid];
        g_msum[m0 + tid] = t;
    }
}

// ===========================================================================
// K2: attention chain on the 2048-element mean vector. One block per b.
// ===========================================================================
__global__ __launch_bounds__(256)
void k_att(const float* __restrict__ conv_w, const float* __restrict__ conv_b)
{
    const int b = blockIdx.x;
    const int n = threadIdx.x;
    __shared__ float sm_m[N_];
    sm_m[n] = g_msum[b * N_ + n] * (1.0f / 32768.0f);
    float stot = 1.f;
    #pragma unroll
    for (int i = 0; i < 3; ++i) {
        __syncthreads();
        float acc = conv_b[i];
        #pragma unroll
        for (int j = 0; j < 5; ++j) {
            const int idx = n + j - 2;
            const float v = (idx >= 0 && idx < N_) ? sm_m[idx] : 0.f;
            acc += v * conv_w[i * 5 + j];
        }
        const float att = 1.0f / (1.0f + __expf(-acc));
        stot *= att;
        __syncthreads();
        sm_m[n] *= att;
    }
    g_s[b * N_ + n] = stot;
}

// ===========================================================================
// K3: cvec[d] = bs_vec @ fc_w[d,:] + fc_b[d]; also tf32-rounded fc_w copy.
// ===========================================================================
__global__ __launch_bounds__(256)
void k_cvec(const float* __restrict__ bs, const float* __restrict__ fc_w,
            const float* __restrict__ fc_b)
{
    const int gw   = (blockIdx.x * blockDim.x + threadIdx.x) >> 5;
    const int lane = threadIdx.x & 31;
    float acc = 0.f;
    for (int k = lane; k < DIM_; k += 32) {
        const float v = fc_w[gw * DIM_ + k];
        acc += bs[k] * v;
        g_fcw[gw * DIM_ + k] = wmma::__float_to_tf32(v);
    }
    #pragma unroll
    for (int off = 16; off; off >>= 1)
        acc += __shfl_xor_sync(0xffffffffu, acc, off);
    if (lane == 0) g_cvec[gw] = acc + fc_b[gw];
}

// ===========================================================================
// K4: out[m,d] = s[m]*(z @ fcw^T)[m,d] + cvec[d]
// mma.sync.m16n8k8.tf32 with ldmatrix-loaded fragments (CUTLASS b16 trick:
// 8x4 b32 tile == 8x8 b16 tile; B "col" operand == fcw's native row-major).
// CTA 128x128, BK=32, 4-stage cp.async ring, XOR-swizzled smem rows
// (conflict-free for both the 16B STS and the LDSM row reads).
// Warp tile 64x32 (2x4 warps): 6 LDSM.x4 + 16 HMMA per k8-step.
// ===========================================================================
#define GBM      128
#define GBN      128
#define GBK      32
#define NCHUNK   (DIM_ / GBK)          // 32
#define GSTAGES  4
#define STG_F    (GBM * GBK)           // 4096 floats = 16 KB per operand stage
#define SMEM_GEMM (2 * GSTAGES * STG_F * 4)   // 131072 B

// swizzled byte offset within a stage tile: row*128B, XOR 16B-group with row%8
__device__ __forceinline__ uint32_t swz(int row, int kg) {
    return (uint32_t)(row * 128 + ((kg ^ (row & 7)) << 4));
}

__global__ __launch_bounds__(256)
void k_gemm_mma(float* __restrict__ out)
{
    extern __shared__ __align__(128) float sm[];
    const uint32_t smem_base = (uint32_t)__cvta_generic_to_shared(sm);

    const int tid  = threadIdx.x;
    const int warp = tid >> 5;
    const int lane = tid & 31;
    const int wm   = warp >> 2;            // 0..1 -> 64 rows m
    const int wn   = warp & 3;             // 0..3 -> 32 cols n
    const int m_cta = blockIdx.y * GBM;
    const int n_cta = blockIdx.x * GBN;

    // ---- loader mapping: thread -> (row, 4 of the 8 16B k-groups)
    const int lrow = tid >> 1;             // 0..127
    const int lkg0 = (tid & 1) * 4;        // 0 or 4
    const float* srcA = &g_z[(m_cta + lrow) * DIM_];
    const float* srcB = &g_fcw[(n_cta + lrow) * DIM_];
    uint32_t dstA[4], dstB[4];
    #pragma unroll
    for (int g = 0; g < 4; ++g) {
        dstA[g] = smem_base + swz(lrow, lkg0 + g);
        dstB[g] = smem_base + GSTAGES * STG_F * 4 + swz(lrow, lkg0 + g);
    }

    // ---- LDSM lane addressing (offsets within a stage tile)
    // A fragment tiles: t0 rows m..m+7 kg, t1 +8 kg, t2 m..m+7 kg+1, t3 +8 kg+1
    const int a_row = wm * 64 + (lane & 7) + ((lane >> 3) & 1) * 8;  // + mt*16
    const int a_kgl = (lane >> 4);                                    // 0/1
    // B tiles: t0 n..n+7 kg, t1 n..n+7 kg+1, t2 n+8.. kg, t3 n+8.. kg+1
    const int b_row = wn * 32 + (lane & 7) + ((lane >> 4) & 1) * 8;  // + bt*16
    const int b_kgl = (lane >> 3) & 1;                                // 0/1

    float acc[4][4][4];
    #pragma unroll
    for (int i = 0; i < 4; ++i)
        #pragma unroll
        for (int j = 0; j < 4; ++j)
            #pragma unroll
            for (int e = 0; e < 4; ++e) acc[i][j][e] = 0.f;

    // ---- prologue: prime 3 stages
    #pragma unroll
    for (int t = 0; t < GSTAGES - 1; ++t) {
        const int k0 = t * GBK;
        #pragma unroll
        for (int g = 0; g < 4; ++g) {
            CP_ASYNC16(dstA[g] + t * STG_F * 4, srcA + k0 + (lkg0 + g) * 4);
            CP_ASYNC16(dstB[g] + t * STG_F * 4, srcB + k0 + (lkg0 + g) * 4);
        }
        CP_COMMIT();
    }

    #pragma unroll 1
    for (int t = 0; t < NCHUNK; ++t) {
        CP_WAIT2();                        // stage t resident
        __syncthreads();

        // prefetch stage t+3 into slot (t+3)%4 (its last consumer was t-1)
        const int u = t + GSTAGES - 1;
        if (u < NCHUNK) {
            const int s2 = (u & (GSTAGES - 1)) * STG_F * 4;
            const int k0 = u * GBK;
            #pragma unroll
            for (int g = 0; g < 4; ++g) {
                CP_ASYNC16(dstA[g] + s2, srcA + k0 + (lkg0 + g) * 4);
                CP_ASYNC16(dstB[g] + s2, srcB + k0 + (lkg0 + g) * 4);
            }
        }
        CP_COMMIT();                       // uniform group count

        const uint32_t aS = smem_base + (t & (GSTAGES - 1)) * STG_F * 4;
        const uint32_t bS = aS + GSTAGES * STG_F * 4;

        // 4 k8-steps per stage, register double-buffered fragments
        uint32_t aF[2][4][4], bF[2][2][4];
        #pragma unroll
        for (int mt = 0; mt < 4; ++mt)
            LDSM_X4(aF[0][mt], aS + swz(a_row + mt * 16, a_kgl));
        #pragma unroll
        for (int bt = 0; bt < 2; ++bt)
            LDSM_X4(bF[0][bt], bS + swz(b_row + bt * 16, b_kgl));

        #pragma unroll
        for (int kk = 0; kk < 4; ++kk) {
            const int cur = kk & 1, nxt = cur ^ 1;
            if (kk < 3) {
                const int kg = (kk + 1) * 2;
                #pragma unroll
                for (int mt = 0; mt < 4; ++mt)
                    LDSM_X4(aF[nxt][mt], aS + swz(a_row + mt * 16, kg + a_kgl));
                #pragma unroll
                for (int bt = 0; bt < 2; ++bt)
                    LDSM_X4(bF[nxt][bt], bS + swz(b_row + bt * 16, kg + b_kgl));
            }
            #pragma unroll
            for (int mt = 0; mt < 4; ++mt) {
                MMA_TF32(acc[mt][0], aF[cur][mt], bF[cur][0][0], bF[cur][0][1]);
                MMA_TF32(acc[mt][1], aF[cur][mt], bF[cur][0][2], bF[cur][0][3]);
                MMA_TF32(acc[mt][2], aF[cur][mt], bF[cur][1][0], bF[cur][1][1]);
                MMA_TF32(acc[mt][3], aF[cur][mt], bF[cur][1][2], bF[cur][1][3]);
            }
        }
    }

    // ---- epilogue: out = s[m]*acc + cvec[d], straight from registers
    const int r  = lane >> 2;              // row within m16 tile
    const int c2 = (lane & 3) * 2;         // col pair within n8 tile
    #pragma unroll
    for (int mt = 0; mt < 4; ++mt) {
        const int row0 = m_cta + wm * 64 + mt * 16 + r;
        const float s0 = g_s[row0];
        const float s1 = g_s[row0 + 8];
        #pragma unroll
        for (int nt = 0; nt < 4; ++nt) {
            const int col = n_cta + wn * 32 + nt * 8 + c2;
            const float2 cv = *(const float2*)&g_cvec[col];
            float2 o0, o1;
            o0.x = s0 * acc[mt][nt][0] + cv.x;
            o0.y = s0 * acc[mt][nt][1] + cv.y;
            o1.x = s1 * acc[mt][nt][2] + cv.x;
            o1.y = s1 * acc[mt][nt][3] + cv.y;
            *(float2*)&out[row0 * DIM_ + col]       = o0;
            *(float2*)&out[(row0 + 8) * DIM_ + col] = o1;
        }
    }
}

// ===========================================================================
extern "C" void kernel_launch(void* const* d_in, const int* in_sizes, int n_in,
                              void* d_out, int out_size)
{
    (void)in_sizes; (void)n_in; (void)out_size;
    const float* x      = (const float*)d_in[0];
    const float* conv_w = (const float*)d_in[1];
    const float* conv_b = (const float*)d_in[2];
    const float* Ws     = (const float*)d_in[3];
    const float* bs     = (const float*)d_in[4];
    const float* fc_w   = (const float*)d_in[5];
    const float* fc_b   = (const float*)d_in[6];
    float* out = (float*)d_out;

    k_reduce<<<M_ / 4, 256>>>((const float4*)x, (const float4*)Ws);
    k_att<<<B_, 256>>>(conv_w, conv_b);
    k_cvec<<<DIM_ / 8, 256>>>(bs, fc_w, fc_b);

    cudaFuncSetAttribute(k_gemm_mma, cudaFuncAttributeMaxDynamicSharedMemorySize,
                         SMEM_GEMM);
    dim3 grid(DIM_ / GBN, M_ / GBM);        // (8, 16) = 128 CTAs, one wave
    k_gemm_mma<<<grid, 256, SMEM_GEMM>>>(out);
}

// round 14
// speedup vs baseline: 1.4477x; 1.0514x over previous
#include <cuda_runtime.h>
#include <cuda_bf16.h>
#include <mma.h>
#include <cstdint>

using namespace nvcuda;

#define B_    8
#define N_    256
#define C_    512
#define HW_   64
#define DIM_  1024
#define M_    (B_ * N_)          // 2048

// ---------------- device scratch (no allocation allowed) -------------------
__device__ float g_z[M_ * DIM_];     // unscaled projections, tf32-rounded (8 MB)
__device__ float g_fcw[DIM_ * DIM_]; // tf32-rounded copy of fc_w (4 MB)
__device__ float g_msum[M_];         // per-(b,n) sum over (C,H,W)
__device__ float g_s[M_];            // a1*a2*a3 per (b,n)
__device__ float g_cvec[DIM_];       // bs_vec @ fc_w^T + fc_b

// ---------------- PTX helpers (all sm_80-era: safe on compute_103) ---------
#define CP_ASYNC16(dst_u32, src_ptr) \
    asm volatile("cp.async.cg.shared.global [%0], [%1], 16;\n" \
                 :: "r"(dst_u32), "l"(src_ptr))
#define CP_COMMIT()  asm volatile("cp.async.commit_group;\n" ::)
#define CP_WAIT2()   asm volatile("cp.async.wait_group 2;\n" ::)

#define LDSM_X4(r, addr) \
    asm volatile("ldmatrix.sync.aligned.m8n8.x4.shared.b16 {%0,%1,%2,%3}, [%4];" \
        : "=r"((r)[0]), "=r"((r)[1]), "=r"((r)[2]), "=r"((r)[3]) : "r"(addr))

#define MMA_TF32(d, a, b0v, b1v) \
    asm volatile("mma.sync.aligned.m16n8k8.row.col.f32.tf32.tf32.f32 " \
        "{%0,%1,%2,%3}, {%4,%5,%6,%7}, {%8,%9}, {%0,%1,%2,%3};" \
        : "+f"((d)[0]), "+f"((d)[1]), "+f"((d)[2]), "+f"((d)[3]) \
        : "r"((a)[0]), "r"((a)[1]), "r"((a)[2]), "r"((a)[3]), \
          "r"(b0v), "r"(b1v))

// ===========================================================================
// K1: single fused pass over x (256 MB, read exactly once).  (unchanged)
// ===========================================================================
__global__ __launch_bounds__(256)
void k_reduce(const float4* __restrict__ x4, const float4* __restrict__ Ws4)
{
    const int m0   = blockIdx.x * 4;
    const int tid  = threadIdx.x;
    const int warp = tid >> 5;
    const int lane = tid & 31;
    const int half = lane >> 4;
    const int hl   = lane & 15;

    float sum0 = 0.f, sum1 = 0.f, sum2 = 0.f, sum3 = 0.f;

    #pragma unroll 1
    for (int it = 0; it < 32; ++it) {
        const int c = it * 16 + warp * 2 + half;
        const float4 w0 = Ws4[c * 32 + hl];
        const float4 w1 = Ws4[c * 32 + 16 + hl];

        float4 xv[4];
        #pragma unroll
        for (int nt = 0; nt < 4; ++nt)
            xv[nt] = x4[((m0 + nt) * C_ + c) * 16 + hl];

        #pragma unroll
        for (int nt = 0; nt < 4; ++nt) {
            const float4 v = xv[nt];
            float z0 = v.x * w0.x + v.y * w0.y + v.z * w0.z + v.w * w0.w;
            float z1 = v.x * w1.x + v.y * w1.y + v.z * w1.z + v.w * w1.w;
            const float ls = (v.x + v.y) + (v.z + v.w);
            if (nt == 0) sum0 += ls; else if (nt == 1) sum1 += ls;
            else if (nt == 2) sum2 += ls; else sum3 += ls;
            #pragma unroll
            for (int off = 8; off; off >>= 1) {
                z0 += __shfl_xor_sync(0xffffffffu, z0, off);
                z1 += __shfl_xor_sync(0xffffffffu, z1, off);
            }
            if (hl == 0) {
                float2 zz = make_float2(wmma::__float_to_tf32(z0),
                                        wmma::__float_to_tf32(z1));
                *(float2*)&g_z[(m0 + nt) * DIM_ + 2 * c] = zz;
            }
        }
    }

    #pragma unroll
    for (int off = 16; off; off >>= 1) {
        sum0 += __shfl_xor_sync(0xffffffffu, sum0, off);
        sum1 += __shfl_xor_sync(0xffffffffu, sum1, off);
        sum2 += __shfl_xor_sync(0xffffffffu, sum2, off);
        sum3 += __shfl_xor_sync(0xffffffffu, sum3, off);
    }
    __shared__ float red[8][4];
    if (lane == 0) {
        red[warp][0] = sum0; red[warp][1] = sum1;
        red[warp][2] = sum2; red[warp][3] = sum3;
    }
    __syncthreads();
    if (tid < 4) {
        float t = 0.f;
        #pragma unroll
        for (int w = 0; w < 8; ++w) t += red[w][tid];
        g_msum[m0 + tid] = t;
    }
}

// ===========================================================================
// K2: attention chain on the 2048-element mean vector. One block per b.
// ===========================================================================
__global__ __launch_bounds__(256)
void k_att(const float* __restrict__ conv_w, const float* __restrict__ conv_b)
{
    const int b = blockIdx.x;
    const int n = threadIdx.x;
    __shared__ float sm_m[N_];
    sm_m[n] = g_msum[b * N_ + n] * (1.0f / 32768.0f);
    float stot = 1.f;
    #pragma unroll
    for (int i = 0; i < 3; ++i) {
        __syncthreads();
        float acc = conv_b[i];
        #pragma unroll
        for (int j = 0; j < 5; ++j) {
            const int idx = n + j - 2;
            const float v = (idx >= 0 && idx < N_) ? sm_m[idx] : 0.f;
            acc += v * conv_w[i * 5 + j];
        }
        const float att = 1.0f / (1.0f + __expf(-acc));
        stot *= att;
        __syncthreads();
        sm_m[n] *= att;
    }
    g_s[b * N_ + n] = stot;
}

// ===========================================================================
// K3: cvec[d] = bs_vec @ fc_w[d,:] + fc_b[d]; also tf32-rounded fc_w copy.
// ===========================================================================
__global__ __launch_bounds__(256)
void k_cvec(const float* __restrict__ bs, const float* __restrict__ fc_w,
            const float* __restrict__ fc_b)
{
    const int gw   = (blockIdx.x * blockDim.x + threadIdx.x) >> 5;
    const int lane = threadIdx.x & 31;
    float acc = 0.f;
    for (int k = lane; k < DIM_; k += 32) {
        const float v = fc_w[gw * DIM_ + k];
        acc += bs[k] * v;
        g_fcw[gw * DIM_ + k] = wmma::__float_to_tf32(v);
    }
    #pragma unroll
    for (int off = 16; off; off >>= 1)
        acc += __shfl_xor_sync(0xffffffffu, acc, off);
    if (lane == 0) g_cvec[gw] = acc + fc_b[gw];
}

// ===========================================================================
// K4: out[m,d] = s[m]*(z @ fcw^T)[m,d] + cvec[d]
// mma.sync.m16n8k8.tf32 + ldmatrix (b16 trick). CTA 128x128, BK=32,
// 4-stage cp.async ring, XOR-swizzled rows. NOW: 512 threads = 16 warps
// (4x4 grid, warp tile 32x32) -> 4 warps/SMSP for latency hiding.
// ===========================================================================
#define GBM      128
#define GBN      128
#define GBK      32
#define NCHUNK   (DIM_ / GBK)          // 32
#define GSTAGES  4
#define STG_F    (GBM * GBK)           // 4096 floats = 16 KB per operand stage
#define SMEM_GEMM (2 * GSTAGES * STG_F * 4)   // 131072 B

// swizzled byte offset within a stage tile: row*128B, XOR 16B-group with row%8
__device__ __forceinline__ uint32_t swz(int row, int kg) {
    return (uint32_t)(row * 128 + ((kg ^ (row & 7)) << 4));
}

__global__ __launch_bounds__(512)
void k_gemm_mma(float* __restrict__ out)
{
    extern __shared__ __align__(128) float sm[];
    const uint32_t smem_base = (uint32_t)__cvta_generic_to_shared(sm);

    const int tid  = threadIdx.x;
    const int warp = tid >> 5;
    const int lane = tid & 31;
    const int wm   = warp >> 2;            // 0..3 -> 32 rows m
    const int wn   = warp & 3;             // 0..3 -> 32 cols n
    const int m_cta = blockIdx.y * GBM;
    const int n_cta = blockIdx.x * GBN;

    // ---- loader mapping: thread -> (row, 2 of the 8 16B k-groups)
    const int lrow = tid >> 2;             // 0..127
    const int lkg0 = (tid & 3) * 2;        // 0,2,4,6
    const float* srcA = &g_z[(m_cta + lrow) * DIM_];
    const float* srcB = &g_fcw[(n_cta + lrow) * DIM_];
    uint32_t dstA[2], dstB[2];
    #pragma unroll
    for (int g = 0; g < 2; ++g) {
        dstA[g] = smem_base + swz(lrow, lkg0 + g);
        dstB[g] = smem_base + GSTAGES * STG_F * 4 + swz(lrow, lkg0 + g);
    }

    // ---- LDSM lane addressing (offsets within a stage tile)
    const int a_row = wm * 32 + (lane & 7) + ((lane >> 3) & 1) * 8;  // + mt*16
    const int a_kgl = (lane >> 4);                                    // 0/1
    const int b_row = wn * 32 + (lane & 7) + ((lane >> 4) & 1) * 8;  // + bt*16
    const int b_kgl = (lane >> 3) & 1;                                // 0/1

    float acc[2][4][4];
    #pragma unroll
    for (int i = 0; i < 2; ++i)
        #pragma unroll
        for (int j = 0; j < 4; ++j)
            #pragma unroll
            for (int e = 0; e < 4; ++e) acc[i][j][e] = 0.f;

    // ---- prologue: prime 3 stages
    #pragma unroll
    for (int t = 0; t < GSTAGES - 1; ++t) {
        const int k0 = t * GBK;
        #pragma unroll
        for (int g = 0; g < 2; ++g) {
            CP_ASYNC16(dstA[g] + t * STG_F * 4, srcA + k0 + (lkg0 + g) * 4);
            CP_ASYNC16(dstB[g] + t * STG_F * 4, srcB + k0 + (lkg0 + g) * 4);
        }
        CP_COMMIT();
    }

    #pragma unroll 1
    for (int t = 0; t < NCHUNK; ++t) {
        CP_WAIT2();                        // stage t resident
        __syncthreads();

        // prefetch stage t+3 into slot (t+3)%4 (its last consumer was t-1)
        const int u = t + GSTAGES - 1;
        if (u < NCHUNK) {
            const int s2 = (u & (GSTAGES - 1)) * STG_F * 4;
            const int k0 = u * GBK;
            #pragma unroll
            for (int g = 0; g < 2; ++g) {
                CP_ASYNC16(dstA[g] + s2, srcA + k0 + (lkg0 + g) * 4);
                CP_ASYNC16(dstB[g] + s2, srcB + k0 + (lkg0 + g) * 4);
            }
        }
        CP_COMMIT();                       // uniform group count

        const uint32_t aS = smem_base + (t & (GSTAGES - 1)) * STG_F * 4;
        const uint32_t bS = aS + GSTAGES * STG_F * 4;

        // 4 k8-steps per stage, register double-buffered fragments
        uint32_t aF[2][2][4], bF[2][2][4];
        #pragma unroll
        for (int mt = 0; mt < 2; ++mt)
            LDSM_X4(aF[0][mt], aS + swz(a_row + mt * 16, a_kgl));
        #pragma unroll
        for (int bt = 0; bt < 2; ++bt)
            LDSM_X4(bF[0][bt], bS + swz(b_row + bt * 16, b_kgl));

        #pragma unroll
        for (int kk = 0; kk < 4; ++kk) {
            const int cur = kk & 1, nxt = cur ^ 1;
            if (kk < 3) {
                const int kg = (kk + 1) * 2;
                #pragma unroll
                for (int mt = 0; mt < 2; ++mt)
                    LDSM_X4(aF[nxt][mt], aS + swz(a_row + mt * 16, kg + a_kgl));
                #pragma unroll
                for (int bt = 0; bt < 2; ++bt)
                    LDSM_X4(bF[nxt][bt], bS + swz(b_row + bt * 16, kg + b_kgl));
            }
            #pragma unroll
            for (int mt = 0; mt < 2; ++mt) {
                MMA_TF32(acc[mt][0], aF[cur][mt], bF[cur][0][0], bF[cur][0][1]);
                MMA_TF32(acc[mt][1], aF[cur][mt], bF[cur][0][2], bF[cur][0][3]);
                MMA_TF32(acc[mt][2], aF[cur][mt], bF[cur][1][0], bF[cur][1][1]);
                MMA_TF32(acc[mt][3], aF[cur][mt], bF[cur][1][2], bF[cur][1][3]);
            }
        }
    }

    // ---- epilogue: out = s[m]*acc + cvec[d], straight from registers
    const int r  = lane >> 2;              // row within m16 tile
    const int c2 = (lane & 3) * 2;         // col pair within n8 tile
    #pragma unroll
    for (int mt = 0; mt < 2; ++mt) {
        const int row0 = m_cta + wm * 32 + mt * 16 + r;
        const float s0 = g_s[row0];
        const float s1 = g_s[row0 + 8];
        #pragma unroll
        for (int nt = 0; nt < 4; ++nt) {
            const int col = n_cta + wn * 32 + nt * 8 + c2;
            const float2 cv = *(const float2*)&g_cvec[col];
            float2 o0, o1;
            o0.x = s0 * acc[mt][nt][0] + cv.x;
            o0.y = s0 * acc[mt][nt][1] + cv.y;
            o1.x = s1 * acc[mt][nt][2] + cv.x;
            o1.y = s1 * acc[mt][nt][3] + cv.y;
            *(float2*)&out[row0 * DIM_ + col]       = o0;
            *(float2*)&out[(row0 + 8) * DIM_ + col] = o1;
        }
    }
}

// ===========================================================================
extern "C" void kernel_launch(void* const* d_in, const int* in_sizes, int n_in,
                              void* d_out, int out_size)
{
    (void)in_sizes; (void)n_in; (void)out_size;
    const float* x      = (const float*)d_in[0];
    const float* conv_w = (const float*)d_in[1];
    const float* conv_b = (const float*)d_in[2];
    const float* Ws     = (const float*)d_in[3];
    const float* bs     = (const float*)d_in[4];
    const float* fc_w   = (const float*)d_in[5];
    const float* fc_b   = (const float*)d_in[6];
    float* out = (float*)d_out;

    k_reduce<<<M_ / 4, 256>>>((const float4*)x, (const float4*)Ws);
    k_att<<<B_, 256>>>(conv_w, conv_b);
    k_cvec<<<DIM_ / 8, 256>>>(bs, fc_w, fc_b);

    cudaFuncSetAttribute(k_gemm_mma, cudaFuncAttributeMaxDynamicSharedMemorySize,
                         SMEM_GEMM);
    dim3 grid(DIM_ / GBN, M_ / GBM);        // (8, 16) = 128 CTAs, one wave
    k_gemm_mma<<<grid, 512, SMEM_GEMM>>>(out);
}

// round 15
// speedup vs baseline: 1.6081x; 1.1108x over previous
#include <cuda_runtime.h>
#include <cuda_fp16.h>
#include <cuda_bf16.h>
#include <cstdint>

#define B_    8
#define N_    256
#define C_    512
#define HW_   64
#define DIM_  1024
#define M_    (B_ * N_)          // 2048

// ---------------- device scratch (no allocation allowed) -------------------
__device__ __half g_zh[M_ * DIM_];     // unscaled projections, fp16 (4 MB)
__device__ __half g_fcwh[DIM_ * DIM_]; // fp16 copy of fc_w (2 MB)
__device__ float  g_msum[M_];          // per-(b,n) sum over (C,H,W)
__device__ float  g_s[M_];             // a1*a2*a3 per (b,n)
__device__ float  g_cvec[DIM_];        // bs_vec @ fc_w^T + fc_b (fp32)

// ---------------- PTX helpers (all sm_80-era: safe on compute_103) ---------
#define CP_ASYNC16(dst_u32, src_ptr) \
    asm volatile("cp.async.cg.shared.global [%0], [%1], 16;\n" \
                 :: "r"(dst_u32), "l"(src_ptr))
#define CP_COMMIT()  asm volatile("cp.async.commit_group;\n" ::)
#define CP_WAIT2()   asm volatile("cp.async.wait_group 2;\n" ::)

#define LDSM_X4(r, addr) \
    asm volatile("ldmatrix.sync.aligned.m8n8.x4.shared.b16 {%0,%1,%2,%3}, [%4];" \
        : "=r"((r)[0]), "=r"((r)[1]), "=r"((r)[2]), "=r"((r)[3]) : "r"(addr))

// fp16 MMA, fp32 accumulate: A 4 regs (16x16), B 2 regs (16x8)
#define MMA_F16(d, a, b0v, b1v) \
    asm volatile("mma.sync.aligned.m16n8k16.row.col.f32.f16.f16.f32 " \
        "{%0,%1,%2,%3}, {%4,%5,%6,%7}, {%8,%9}, {%0,%1,%2,%3};" \
        : "+f"((d)[0]), "+f"((d)[1]), "+f"((d)[2]), "+f"((d)[3]) \
        : "r"((a)[0]), "r"((a)[1]), "r"((a)[2]), "r"((a)[3]), \
          "r"(b0v), "r"(b1v))

// ===========================================================================
// K1: single fused pass over x (256 MB, read exactly once).
// ===========================================================================
__global__ __launch_bounds__(256)
void k_reduce(const float4* __restrict__ x4, const float4* __restrict__ Ws4)
{
    const int m0   = blockIdx.x * 4;
    const int tid  = threadIdx.x;
    const int warp = tid >> 5;
    const int lane = tid & 31;
    const int half = lane >> 4;
    const int hl   = lane & 15;

    float sum0 = 0.f, sum1 = 0.f, sum2 = 0.f, sum3 = 0.f;

    #pragma unroll 1
    for (int it = 0; it < 32; ++it) {
        const int c = it * 16 + warp * 2 + half;
        const float4 w0 = Ws4[c * 32 + hl];
        const float4 w1 = Ws4[c * 32 + 16 + hl];

        float4 xv[4];
        #pragma unroll
        for (int nt = 0; nt < 4; ++nt)
            xv[nt] = x4[((m0 + nt) * C_ + c) * 16 + hl];

        #pragma unroll
        for (int nt = 0; nt < 4; ++nt) {
            const float4 v = xv[nt];
            float z0 = v.x * w0.x + v.y * w0.y + v.z * w0.z + v.w * w0.w;
            float z1 = v.x * w1.x + v.y * w1.y + v.z * w1.z + v.w * w1.w;
            const float ls = (v.x + v.y) + (v.z + v.w);
            if (nt == 0) sum0 += ls; else if (nt == 1) sum1 += ls;
            else if (nt == 2) sum2 += ls; else sum3 += ls;
            #pragma unroll
            for (int off = 8; off; off >>= 1) {
                z0 += __shfl_xor_sync(0xffffffffu, z0, off);
                z1 += __shfl_xor_sync(0xffffffffu, z1, off);
            }
            if (hl == 0) {
                *(__half2*)&g_zh[(m0 + nt) * DIM_ + 2 * c] =
                    __floats2half2_rn(z0, z1);
            }
        }
    }

    #pragma unroll
    for (int off = 16; off; off >>= 1) {
        sum0 += __shfl_xor_sync(0xffffffffu, sum0, off);
        sum1 += __shfl_xor_sync(0xffffffffu, sum1, off);
        sum2 += __shfl_xor_sync(0xffffffffu, sum2, off);
        sum3 += __shfl_xor_sync(0xffffffffu, sum3, off);
    }
    __shared__ float red[8][4];
    if (lane == 0) {
        red[warp][0] = sum0; red[warp][1] = sum1;
        red[warp][2] = sum2; red[warp][3] = sum3;
    }
    __syncthreads();
    if (tid < 4) {
        float t = 0.f;
        #pragma unroll
        for (int w = 0; w < 8; ++w) t += red[w][tid];
        g_msum[m0 + tid] = t;
    }
}

// ===========================================================================
// K2: attention chain on the 2048-element mean vector. One block per b.
// ===========================================================================
__global__ __launch_bounds__(256)
void k_att(const float* __restrict__ conv_w, const float* __restrict__ conv_b)
{
    const int b = blockIdx.x;
    const int n = threadIdx.x;
    __shared__ float sm_m[N_];
    sm_m[n] = g_msum[b * N_ + n] * (1.0f / 32768.0f);
    float stot = 1.f;
    #pragma unroll
    for (int i = 0; i < 3; ++i) {
        __syncthreads();
        float acc = conv_b[i];
        #pragma unroll
        for (int j = 0; j < 5; ++j) {
            const int idx = n + j - 2;
            const float v = (idx >= 0 && idx < N_) ? sm_m[idx] : 0.f;
            acc += v * conv_w[i * 5 + j];
        }
        const float att = 1.0f / (1.0f + __expf(-acc));
        stot *= att;
        __syncthreads();
        sm_m[n] *= att;
    }
    g_s[b * N_ + n] = stot;
}

// ===========================================================================
// K3: cvec[d] = bs_vec @ fc_w[d,:] + fc_b[d] (fp32); fp16 copy of fc_w.
// ===========================================================================
__global__ __launch_bounds__(256)
void k_cvec(const float* __restrict__ bs, const float* __restrict__ fc_w,
            const float* __restrict__ fc_b)
{
    const int gw   = (blockIdx.x * blockDim.x + threadIdx.x) >> 5;
    const int lane = threadIdx.x & 31;
    float acc = 0.f;
    for (int k = lane; k < DIM_; k += 32) {
        const float v = fc_w[gw * DIM_ + k];
        acc += bs[k] * v;
        g_fcwh[gw * DIM_ + k] = __float2half_rn(v);
    }
    #pragma unroll
    for (int off = 16; off; off >>= 1)
        acc += __shfl_xor_sync(0xffffffffu, acc, off);
    if (lane == 0) g_cvec[gw] = acc + fc_b[gw];
}

// ===========================================================================
// K4: out[m,d] = s[m]*(z @ fcw^T)[m,d] + cvec[d]
// fp16 mma.m16n8k16 + ldmatrix. CTA 128x128, BK=64 fp16 (=128B rows, same
// proven swizzle), 4-stage cp.async ring, 512 threads = 16 warps (4x4,
// warp tile 32x32). Half the LDSM+HMMA instructions of the tf32 version.
// ===========================================================================
#define GBM      128
#define GBN      128
#define GBK      64                     // fp16 per k-chunk: 128 bytes/row
#define NCHUNK   (DIM_ / GBK)           // 16
#define GSTAGES  4
#define STG_B    (GBM * 128)            // 16384 bytes per operand stage
#define SMEM_GEMM (2 * GSTAGES * STG_B) // 131072 B

// swizzled byte offset within a stage tile: row*128B, XOR 16B-group with row%8
__device__ __forceinline__ uint32_t swz(int row, int kg) {
    return (uint32_t)(row * 128 + ((kg ^ (row & 7)) << 4));
}

__global__ __launch_bounds__(512)
void k_gemm_mma(float* __restrict__ out)
{
    extern __shared__ __align__(128) char smc[];
    const uint32_t smem_base = (uint32_t)__cvta_generic_to_shared(smc);

    const int tid  = threadIdx.x;
    const int warp = tid >> 5;
    const int lane = tid & 31;
    const int wm   = warp >> 2;            // 0..3 -> 32 rows m
    const int wn   = warp & 3;             // 0..3 -> 32 cols n
    const int m_cta = blockIdx.y * GBM;
    const int n_cta = blockIdx.x * GBN;

    // ---- loader mapping: thread -> (row, 2 of the 8 16B k-groups)
    const int lrow = tid >> 2;             // 0..127
    const int lkg0 = (tid & 3) * 2;        // 0,2,4,6
    const __half* srcA = &g_zh[(m_cta + lrow) * DIM_];
    const __half* srcB = &g_fcwh[(n_cta + lrow) * DIM_];
    uint32_t dstA[2], dstB[2];
    #pragma unroll
    for (int g = 0; g < 2; ++g) {
        dstA[g] = smem_base + swz(lrow, lkg0 + g);
        dstB[g] = smem_base + GSTAGES * STG_B + swz(lrow, lkg0 + g);
    }

    // ---- LDSM lane addressing (offsets within a stage tile)
    // A x4 tiles: {m0-7,kg},{m8-15,kg},{m0-7,kg+1},{m8-15,kg+1} = a0..a3 (k16)
    const int a_row = wm * 32 + (lane & 7) + ((lane >> 3) & 1) * 8;  // + mt*16
    const int a_kgl = (lane >> 4);                                    // 0/1
    // B x4 tiles: {n0-7,kg},{n0-7,kg+1},{n8-15,kg},{n8-15,kg+1}
    //  -> regs {0,1} = n-tile k16, regs {2,3} = (n+8)-tile k16
    const int b_row = wn * 32 + (lane & 7) + ((lane >> 4) & 1) * 8;  // + bt*16
    const int b_kgl = (lane >> 3) & 1;                                // 0/1

    float acc[2][4][4];
    #pragma unroll
    for (int i = 0; i < 2; ++i)
        #pragma unroll
        for (int j = 0; j < 4; ++j)
            #pragma unroll
            for (int e = 0; e < 4; ++e) acc[i][j][e] = 0.f;

    // ---- prologue: prime 3 stages
    #pragma unroll
    for (int t = 0; t < GSTAGES - 1; ++t) {
        const int k0 = t * GBK;
        #pragma unroll
        for (int g = 0; g < 2; ++g) {
            CP_ASYNC16(dstA[g] + t * STG_B, srcA + k0 + (lkg0 + g) * 8);
            CP_ASYNC16(dstB[g] + t * STG_B, srcB + k0 + (lkg0 + g) * 8);
        }
        CP_COMMIT();
    }

    #pragma unroll 1
    for (int t = 0; t < NCHUNK; ++t) {
        CP_WAIT2();                        // stage t resident
        __syncthreads();

        // prefetch stage t+3 into slot (t+3)%4 (its last consumer was t-1)
        const int u = t + GSTAGES - 1;
        if (u < NCHUNK) {
            const int s2 = (u & (GSTAGES - 1)) * STG_B;
            const int k0 = u * GBK;
            #pragma unroll
            for (int g = 0; g < 2; ++g) {
                CP_ASYNC16(dstA[g] + s2, srcA + k0 + (lkg0 + g) * 8);
                CP_ASYNC16(dstB[g] + s2, srcB + k0 + (lkg0 + g) * 8);
            }
        }
        CP_COMMIT();                       // uniform group count

        const uint32_t aS = smem_base + (t & (GSTAGES - 1)) * STG_B;
        const uint32_t bS = aS + GSTAGES * STG_B;

        // 4 k16-steps per stage (k-groups {2kk, 2kk+1}), reg double-buffered
        uint32_t aF[2][2][4], bF[2][2][4];
        #pragma unroll
        for (int mt = 0; mt < 2; ++mt)
            LDSM_X4(aF[0][mt], aS + swz(a_row + mt * 16, a_kgl));
        #pragma unroll
        for (int bt = 0; bt < 2; ++bt)
            LDSM_X4(bF[0][bt], bS + swz(b_row + bt * 16, b_kgl));

        #pragma unroll
        for (int kk = 0; kk < 4; ++kk) {
            const int cur = kk & 1, nxt = cur ^ 1;
            if (kk < 3) {
                const int kg = (kk + 1) * 2;
                #pragma unroll
                for (int mt = 0; mt < 2; ++mt)
                    LDSM_X4(aF[nxt][mt], aS + swz(a_row + mt * 16, kg + a_kgl));
                #pragma unroll
                for (int bt = 0; bt < 2; ++bt)
                    LDSM_X4(bF[nxt][bt], bS + swz(b_row + bt * 16, kg + b_kgl));
            }
            #pragma unroll
            for (int mt = 0; mt < 2; ++mt) {
                MMA_F16(acc[mt][0], aF[cur][mt], bF[cur][0][0], bF[cur][0][1]);
                MMA_F16(acc[mt][1], aF[cur][mt], bF[cur][0][2], bF[cur][0][3]);
                MMA_F16(acc[mt][2], aF[cur][mt], bF[cur][1][0], bF[cur][1][1]);
                MMA_F16(acc[mt][3], aF[cur][mt], bF[cur][1][2], bF[cur][1][3]);
            }
        }
    }

    // ---- epilogue: out = s[m]*acc + cvec[d], straight from registers
    const int r  = lane >> 2;              // row within m16 tile
    const int c2 = (lane & 3) * 2;         // col pair within n8 tile
    #pragma unroll
    for (int mt = 0; mt < 2; ++mt) {
        const int row0 = m_cta + wm * 32 + mt * 16 + r;
        const float s0 = g_s[row0];
        const float s1 = g_s[row0 + 8];
        #pragma unroll
        for (int nt = 0; nt < 4; ++nt) {
            const int col = n_cta + wn * 32 + nt * 8 + c2;
            const float2 cv = *(const float2*)&g_cvec[col];
            float2 o0, o1;
            o0.x = s0 * acc[mt][nt][0] + cv.x;
            o0.y = s0 * acc[mt][nt][1] + cv.y;
            o1.x = s1 * acc[mt][nt][2] + cv.x;
            o1.y = s1 * acc[mt][nt][3] + cv.y;
            *(float2*)&out[row0 * DIM_ + col]       = o0;
            *(float2*)&out[(row0 + 8) * DIM_ + col] = o1;
        }
    }
}

// ===========================================================================
extern "C" void kernel_launch(void* const* d_in, const int* in_sizes, int n_in,
                              void* d_out, int out_size)
{
    (void)in_sizes; (void)n_in; (void)out_size;
    const float* x      = (const float*)d_in[0];
    const float* conv_w = (const float*)d_in[1];
    const float* conv_b = (const float*)d_in[2];
    const float* Ws     = (const float*)d_in[3];
    const float* bs     = (const float*)d_in[4];
    const float* fc_w   = (const float*)d_in[5];
    const float* fc_b   = (const float*)d_in[6];
    float* out = (float*)d_out;

    k_reduce<<<M_ / 4, 256>>>((const float4*)x, (const float4*)Ws);
    k_att<<<B_, 256>>>(conv_w, conv_b);
    k_cvec<<<DIM_ / 8, 256>>>(bs, fc_w, fc_b);

    cudaFuncSetAttribute(k_gemm_mma, cudaFuncAttributeMaxDynamicSharedMemorySize,
                         SMEM_GEMM);
    dim3 grid(DIM_ / GBN, M_ / GBM);        // (8, 16) = 128 CTAs, one wave
    k_gemm_mma<<<grid, 512, SMEM_GEMM>>>(out);
}